// round 2
// baseline (speedup 1.0000x reference)
#include <cuda_runtime.h>
#include <math.h>

typedef unsigned long long u64;

#define B_ 4
#define L_ 1024
#define D_ 768
#define H_ 12
#define NE_ 42
#define M_ 4
#define P_ 512
#define NL_ 97
#define NLP_ 128
#define KS_ 12
#define NPAIR_ (B_*P_)          // 2048
#define KBI_ 49152              // D_*64

// ---------------- device scratch (no allocation allowed) ----------------
__device__ __align__(16) float g_ent_emb[B_ * NE_ * D_];           // [b,e,d]
__device__ __align__(16) float g_ent_att[B_ * NE_ * L_ * H_];      // [b,e,l,h]
__device__ __align__(16) float g_pair_att[NPAIR_ * L_];            // [np,l]
__device__ __align__(16) float g_rs[NPAIR_ * D_];
__device__ __align__(16) float g_zs[NPAIR_ * D_];
__device__ __align__(16) float g_zo[NPAIR_ * D_];
__device__ __align__(16) float g_Wb[KBI_ * NLP_];                  // padded W_bi
__device__ __align__(16) float g_part[KS_ * NPAIR_ * NL_];

// ---------------- packed f32x2 helpers ----------------
__device__ __forceinline__ u64 fma2(u64 a, u64 b, u64 c) {
    u64 d;
    asm("fma.rn.f32x2 %0, %1, %2, %3;" : "=l"(d) : "l"(a), "l"(b), "l"(c));
    return d;
}
__device__ __forceinline__ u64 pack2(float x, float y) {
    u64 d;
    asm("mov.b64 %0, {%1, %2};" : "=l"(d) : "f"(x), "f"(y));
    return d;
}
__device__ __forceinline__ float2 unpack2(u64 a) {
    float2 r;
    asm("mov.b64 {%0, %1}, %2;" : "=f"(r.x), "=f"(r.y) : "l"(a));
    return r;
}

// ---------------- K0: pad W_bi [49152,97] -> [49152,128] ----------------
__global__ void k_wpad(const float* __restrict__ Wbi) {
    int i = blockIdx.x * blockDim.x + threadIdx.x;
    if (i < KBI_ * NLP_) {
        int r = i >> 7, n = i & 127;
        g_Wb[i] = (n < NL_) ? Wbi[(size_t)r * NL_ + n] : 0.0f;
    }
}

// ---------------- K1: entity embeds = logsumexp over 4 mention tokens ----------------
__global__ void k_ent_emb(const float* __restrict__ seq, const int* __restrict__ mpos) {
    int be = blockIdx.x;
    int b = be / NE_;
    int p0 = mpos[be*M_+0]+1, p1 = mpos[be*M_+1]+1, p2 = mpos[be*M_+2]+1, p3 = mpos[be*M_+3]+1;
    const float* s = seq + (size_t)b * L_ * D_;
    for (int d = threadIdx.x; d < D_; d += blockDim.x) {
        float x0 = s[(size_t)p0*D_+d], x1 = s[(size_t)p1*D_+d];
        float x2 = s[(size_t)p2*D_+d], x3 = s[(size_t)p3*D_+d];
        float mx = fmaxf(fmaxf(x0,x1), fmaxf(x2,x3));
        float su = expf(x0-mx)+expf(x1-mx)+expf(x2-mx)+expf(x3-mx);
        g_ent_emb[(size_t)be*D_+d] = mx + logf(su);
    }
}

// ---------------- K2: entity attention = mean over 4 rows, stored [b,e,l,h] ----------------
__global__ void k_ent_att(const float* __restrict__ att, const int* __restrict__ mpos) {
    int idx = blockIdx.x;
    int be = idx / H_, h = idx % H_;
    int b = be / NE_;
    int p0 = mpos[be*M_+0]+1, p1 = mpos[be*M_+1]+1, p2 = mpos[be*M_+2]+1, p3 = mpos[be*M_+3]+1;
    const float* a = att + ((size_t)b*H_ + h) * L_ * L_;
    float* o = g_ent_att + (size_t)be * L_ * H_ + h;
    for (int l = threadIdx.x; l < L_; l += blockDim.x) {
        o[(size_t)l*H_] = 0.25f * (a[(size_t)p0*L_+l] + a[(size_t)p1*L_+l] +
                                   a[(size_t)p2*L_+l] + a[(size_t)p3*L_+l]);
    }
}

// ---------------- K3: normalized per-pair context attention ----------------
__global__ void k_pair_att(const int* __restrict__ hts) {
    int bp = blockIdx.x;
    int b = bp / P_;
    int hi = hts[bp*2+0], ti = hts[bp*2+1];
    const float* ei = g_ent_att + (size_t)(b*NE_ + hi) * L_ * H_;
    const float* ej = g_ent_att + (size_t)(b*NE_ + ti) * L_ * H_;
    float v[4];
    float loc = 0.0f;
    #pragma unroll
    for (int r = 0; r < 4; r++) {
        int l = threadIdx.x + r * 256;
        const float* pi = ei + (size_t)l * H_;
        const float* pj = ej + (size_t)l * H_;
        float acc = 0.0f;
        #pragma unroll
        for (int h = 0; h < H_; h++) acc += pi[h] * pj[h];
        acc *= (1.0f / (float)H_);
        v[r] = acc;
        loc += acc;
    }
    __shared__ float red[256];
    red[threadIdx.x] = loc;
    __syncthreads();
    for (int s = 128; s > 0; s >>= 1) {
        if (threadIdx.x < s) red[threadIdx.x] += red[threadIdx.x + s];
        __syncthreads();
    }
    float scale = 1.0f / (red[0] + 1e-5f);
    #pragma unroll
    for (int r = 0; r < 4; r++)
        g_pair_att[(size_t)bp*L_ + threadIdx.x + r*256] = v[r] * scale;
}

// ---------------- K4: rs = pair_att @ seq (per-batch), 128x128x16 fp32x2 GEMM ----------------
__global__ void k_rs(const float* __restrict__ seq) {
    __shared__ float As[16][128];
    __shared__ float Bs[16][128];
    int t = threadIdx.x;
    int m0 = blockIdx.y * 128, n0 = blockIdx.x * 128;
    int b = m0 / P_;
    const float* Bg = seq + (size_t)b * L_ * D_;
    const float* Ag = g_pair_att + (size_t)m0 * L_;
    int tm = t / 16, tn = t % 16;
    int arow = t >> 1, acol8 = (t & 1) * 8;
    int brow = t >> 4, bcol8 = (t & 15) * 8;
    u64 acc[8][4];
    #pragma unroll
    for (int i = 0; i < 8; i++)
        #pragma unroll
        for (int j = 0; j < 4; j++) acc[i][j] = 0ull;

    for (int k0 = 0; k0 < L_; k0 += 16) {
        float4 a0 = *(const float4*)(Ag + (size_t)arow*L_ + k0 + acol8);
        float4 a1 = *(const float4*)(Ag + (size_t)arow*L_ + k0 + acol8 + 4);
        float4 b0 = *(const float4*)(Bg + (size_t)(k0+brow)*D_ + n0 + bcol8);
        float4 b1 = *(const float4*)(Bg + (size_t)(k0+brow)*D_ + n0 + bcol8 + 4);
        __syncthreads();
        As[acol8+0][arow]=a0.x; As[acol8+1][arow]=a0.y; As[acol8+2][arow]=a0.z; As[acol8+3][arow]=a0.w;
        As[acol8+4][arow]=a1.x; As[acol8+5][arow]=a1.y; As[acol8+6][arow]=a1.z; As[acol8+7][arow]=a1.w;
        *(float4*)&Bs[brow][bcol8]   = b0;
        *(float4*)&Bs[brow][bcol8+4] = b1;
        __syncthreads();
        #pragma unroll
        for (int kk = 0; kk < 16; kk++) {
            float4 aA = *(const float4*)&As[kk][tm*8];
            float4 aB = *(const float4*)&As[kk][tm*8+4];
            ulonglong2 q0 = *(const ulonglong2*)&Bs[kk][tn*8];
            ulonglong2 q1 = *(const ulonglong2*)&Bs[kk][tn*8+4];
            u64 bv0=q0.x, bv1=q0.y, bv2=q1.x, bv3=q1.y;
            float am[8] = {aA.x,aA.y,aA.z,aA.w,aB.x,aB.y,aB.z,aB.w};
            #pragma unroll
            for (int i = 0; i < 8; i++) {
                u64 pa = pack2(am[i], am[i]);
                acc[i][0] = fma2(pa, bv0, acc[i][0]);
                acc[i][1] = fma2(pa, bv1, acc[i][1]);
                acc[i][2] = fma2(pa, bv2, acc[i][2]);
                acc[i][3] = fma2(pa, bv3, acc[i][3]);
            }
        }
    }
    #pragma unroll
    for (int i = 0; i < 8; i++) {
        float* out = g_rs + (size_t)(m0 + tm*8 + i) * D_ + n0 + tn*8;
        #pragma unroll
        for (int j = 0; j < 4; j++) {
            float2 v = unpack2(acc[i][j]);
            out[2*j] = v.x; out[2*j+1] = v.y;
        }
    }
}

// ---------------- K5: extractors zs/zo = tanh([ent|rs] @ W + b) ----------------
__global__ void k_ext(const int* __restrict__ hts,
                      const float* __restrict__ Wh, const float* __restrict__ bh,
                      const float* __restrict__ Wt, const float* __restrict__ bt) {
    __shared__ float As[16][128];
    __shared__ float Bs[16][128];
    int side = blockIdx.z;
    const float* W    = side ? Wt : Wh;
    const float* bias = side ? bt : bh;
    float* Cout       = side ? g_zo : g_zs;
    int t = threadIdx.x;
    int m0 = blockIdx.y * 128, n0 = blockIdx.x * 128;
    int tm = t / 16, tn = t % 16;
    int arow = t >> 1, acol8 = (t & 1) * 8;
    int brow = t >> 4, bcol8 = (t & 15) * 8;
    int np = m0 + arow;
    int b = np / P_;
    int eidx = hts[np*2 + side];
    const float* A0 = g_ent_emb + (size_t)(b*NE_ + eidx) * D_;
    const float* A1 = g_rs + (size_t)np * D_;
    u64 acc[8][4];
    #pragma unroll
    for (int i = 0; i < 8; i++)
        #pragma unroll
        for (int j = 0; j < 4; j++) acc[i][j] = 0ull;

    for (int k0 = 0; k0 < 2*D_; k0 += 16) {
        const float* Arow = (k0 < D_) ? (A0 + k0) : (A1 + (k0 - D_));
        float4 a0 = *(const float4*)(Arow + acol8);
        float4 a1 = *(const float4*)(Arow + acol8 + 4);
        float4 b0 = *(const float4*)(W + (size_t)(k0+brow)*D_ + n0 + bcol8);
        float4 b1 = *(const float4*)(W + (size_t)(k0+brow)*D_ + n0 + bcol8 + 4);
        __syncthreads();
        As[acol8+0][arow]=a0.x; As[acol8+1][arow]=a0.y; As[acol8+2][arow]=a0.z; As[acol8+3][arow]=a0.w;
        As[acol8+4][arow]=a1.x; As[acol8+5][arow]=a1.y; As[acol8+6][arow]=a1.z; As[acol8+7][arow]=a1.w;
        *(float4*)&Bs[brow][bcol8]   = b0;
        *(float4*)&Bs[brow][bcol8+4] = b1;
        __syncthreads();
        #pragma unroll
        for (int kk = 0; kk < 16; kk++) {
            float4 aA = *(const float4*)&As[kk][tm*8];
            float4 aB = *(const float4*)&As[kk][tm*8+4];
            ulonglong2 q0 = *(const ulonglong2*)&Bs[kk][tn*8];
            ulonglong2 q1 = *(const ulonglong2*)&Bs[kk][tn*8+4];
            u64 bv0=q0.x, bv1=q0.y, bv2=q1.x, bv3=q1.y;
            float am[8] = {aA.x,aA.y,aA.z,aA.w,aB.x,aB.y,aB.z,aB.w};
            #pragma unroll
            for (int i = 0; i < 8; i++) {
                u64 pa = pack2(am[i], am[i]);
                acc[i][0] = fma2(pa, bv0, acc[i][0]);
                acc[i][1] = fma2(pa, bv1, acc[i][1]);
                acc[i][2] = fma2(pa, bv2, acc[i][2]);
                acc[i][3] = fma2(pa, bv3, acc[i][3]);
            }
        }
    }
    #pragma unroll
    for (int i = 0; i < 8; i++) {
        float* out = Cout + (size_t)(m0 + tm*8 + i) * D_ + n0 + tn*8;
        #pragma unroll
        for (int j = 0; j < 4; j++) {
            float2 v = unpack2(acc[i][j]);
            int n = n0 + tn*8 + 2*j;
            out[2*j]   = tanhf(v.x + bias[n]);
            out[2*j+1] = tanhf(v.y + bias[n+1]);
        }
    }
}

// ---------------- K6: bilinear partials, on-the-fly rank-1 A tiles ----------------
// block: 64 pairs x 128 padded cols, one k-block (kk) of the 12. grid (32, 12).
__global__ void k_bil() {
    extern __shared__ float sm[];
    float* Ws = sm;               // [64][128]
    float* Zs = sm + 64*128;      // [i][m]  64x64
    float* Zo = Zs + 64*64;       // [j][m]  64x64
    int t = threadIdx.x;
    int pb = blockIdx.x;          // pair block (64 pairs)
    int kk = blockIdx.y;          // k-block
    int m0 = pb * 64;

    {   // load zs/zo tiles transposed
        int m = t >> 2, c0 = (t & 3) * 16;
        const float* s1 = g_zs + (size_t)(m0+m)*D_ + kk*64 + c0;
        const float* s2 = g_zo + (size_t)(m0+m)*D_ + kk*64 + c0;
        #pragma unroll
        for (int q = 0; q < 16; q++) {
            Zs[(c0+q)*64 + m] = s1[q];
            Zo[(c0+q)*64 + m] = s2[q];
        }
    }
    __syncthreads();

    int tm = t / 16, tn = t % 16;      // tm: 4 pairs, tn: 8 cols
    u64 acc[4][4];
    #pragma unroll
    for (int p = 0; p < 4; p++)
        #pragma unroll
        for (int q = 0; q < 4; q++) acc[p][q] = 0ull;

    int wj = t >> 2, wc0 = (t & 3) * 32;
    for (int i = 0; i < 64; i++) {
        __syncthreads();
        {   // load W tile rows (kk*64+i)*64 + j, all 128 padded cols
            const float4* src = (const float4*)(g_Wb + ((size_t)((kk*64 + i)*64 + wj)) * NLP_ + wc0);
            float4* dst = (float4*)&Ws[wj*NLP_ + wc0];
            #pragma unroll
            for (int q = 0; q < 8; q++) dst[q] = src[q];
        }
        __syncthreads();
        float4 c4 = *(const float4*)&Zs[i*64 + tm*4];
        float cm[4] = {c4.x, c4.y, c4.z, c4.w};
        #pragma unroll 8
        for (int j = 0; j < 64; j++) {
            ulonglong2 q0 = *(const ulonglong2*)&Ws[j*NLP_ + tn*8];
            ulonglong2 q1 = *(const ulonglong2*)&Ws[j*NLP_ + tn*8 + 4];
            u64 w0=q0.x, w1=q0.y, w2=q1.x, w3=q1.y;
            float4 z4 = *(const float4*)&Zo[j*64 + tm*4];
            float zm[4] = {z4.x, z4.y, z4.z, z4.w};
            #pragma unroll
            for (int p = 0; p < 4; p++) {
                float a = cm[p] * zm[p];
                u64 pa = pack2(a, a);
                acc[p][0] = fma2(pa, w0, acc[p][0]);
                acc[p][1] = fma2(pa, w1, acc[p][1]);
                acc[p][2] = fma2(pa, w2, acc[p][2]);
                acc[p][3] = fma2(pa, w3, acc[p][3]);
            }
        }
    }
    #pragma unroll
    for (int p = 0; p < 4; p++) {
        float* out = g_part + ((size_t)kk * NPAIR_ + m0 + tm*4 + p) * NL_;
        #pragma unroll
        for (int q = 0; q < 4; q++) {
            float2 v = unpack2(acc[p][q]);
            int n = tn*8 + 2*q;
            if (n   < NL_) out[n]   = v.x;
            if (n+1 < NL_) out[n+1] = v.y;
        }
    }
}

// ---------------- K7: reduce K-splits + bias ----------------
__global__ void k_red(const float* __restrict__ bbi, float* __restrict__ out) {
    int i = blockIdx.x * blockDim.x + threadIdx.x;
    if (i < NPAIR_ * NL_) {
        int n = i % NL_;
        float s = bbi[n];
        #pragma unroll
        for (int k = 0; k < KS_; k++) s += g_part[(size_t)k * NPAIR_ * NL_ + i];
        out[i] = s;
    }
}

extern "C" void kernel_launch(void* const* d_in, const int* in_sizes, int n_in,
                              void* d_out, int out_size) {
    const float* seq  = (const float*)d_in[0];
    const float* att  = (const float*)d_in[1];
    const int*   mpos = (const int*)d_in[2];
    const int*   hts  = (const int*)d_in[3];
    const float* Wh   = (const float*)d_in[4];
    const float* bh   = (const float*)d_in[5];
    const float* Wt   = (const float*)d_in[6];
    const float* bt   = (const float*)d_in[7];
    const float* Wbi  = (const float*)d_in[8];
    const float* bbi  = (const float*)d_in[9];
    float* out = (float*)d_out;

    cudaFuncSetAttribute(k_bil, cudaFuncAttributeMaxDynamicSharedMemorySize, 65536);

    k_wpad<<<(KBI_*NLP_ + 255)/256, 256>>>(Wbi);
    k_ent_emb<<<B_*NE_, 256>>>(seq, mpos);
    k_ent_att<<<B_*NE_*H_, 256>>>(att, mpos);
    k_pair_att<<<NPAIR_, 256>>>(hts);
    k_rs<<<dim3(6, 16), 256>>>(seq);
    k_ext<<<dim3(6, 16, 2), 256>>>(hts, Wh, bh, Wt, bt);
    k_bil<<<dim3(32, 12), 256, 65536>>>();
    k_red<<<(NPAIR_*NL_ + 255)/256, 256>>>(bbi, out);
}

// round 4
// speedup vs baseline: 1.5122x; 1.5122x over previous
#include <cuda_runtime.h>
#include <stdint.h>
#include <math.h>

typedef unsigned long long u64;

#define B_ 4
#define L_ 1024
#define D_ 768
#define H_ 12
#define NE_ 42
#define M_ 4
#define P_ 512
#define NL_ 97
#define NLP_ 112
#define KS_ 24
#define NPAIR_ (B_*P_)          // 2048
#define KBI_ 49152              // D_*64

// ---------------- device scratch (no allocation allowed) ----------------
__device__ __align__(16) float g_ent_emb[B_ * NE_ * D_];           // [b,e,d]
__device__ __align__(16) float g_ent_att[B_ * NE_ * L_ * H_];      // [b,e,l,h]
__device__ __align__(16) float g_pair_att[NPAIR_ * L_];            // [np,l]
__device__ __align__(16) float g_rs[NPAIR_ * D_];
__device__ __align__(16) float g_zs[NPAIR_ * D_];
__device__ __align__(16) float g_zo[NPAIR_ * D_];
__device__ __align__(16) float g_Wb[(size_t)KBI_ * NLP_];          // padded W_bi
__device__ __align__(16) float g_part[(size_t)KS_ * NPAIR_ * NL_];

// ---------------- packed f32x2 helpers ----------------
__device__ __forceinline__ u64 fma2(u64 a, u64 b, u64 c) {
    u64 d;
    asm("fma.rn.f32x2 %0, %1, %2, %3;" : "=l"(d) : "l"(a), "l"(b), "l"(c));
    return d;
}
__device__ __forceinline__ u64 pack2(float x, float y) {
    u64 d;
    asm("mov.b64 %0, {%1, %2};" : "=l"(d) : "f"(x), "f"(y));
    return d;
}
__device__ __forceinline__ float2 unpack2(u64 a) {
    float2 r;
    asm("mov.b64 {%0, %1}, %2;" : "=f"(r.x), "=f"(r.y) : "l"(a));
    return r;
}

// ---------------- cp.async helpers ----------------
__device__ __forceinline__ void cpa16(unsigned int saddr, const void* gaddr) {
    asm volatile("cp.async.cg.shared.global [%0], [%1], 16;" :: "r"(saddr), "l"(gaddr));
}
__device__ __forceinline__ void cpa_commit() {
    asm volatile("cp.async.commit_group;");
}
template <int N>
__device__ __forceinline__ void cpa_wait() {
    asm volatile("cp.async.wait_group %0;" :: "n"(N));
}

// ---------------- K0: pad W_bi [49152,97] -> [49152,112] ----------------
__global__ void k_wpad(const float* __restrict__ Wbi) {
    int i = blockIdx.x * blockDim.x + threadIdx.x;
    if (i < KBI_ * NLP_) {
        int r = i / NLP_, n = i % NLP_;
        g_Wb[i] = (n < NL_) ? Wbi[(size_t)r * NL_ + n] : 0.0f;
    }
}

// ---------------- K1: entity embeds = logsumexp over 4 mention tokens ----------------
__global__ void k_ent_emb(const float* __restrict__ seq, const int* __restrict__ mpos) {
    int be = blockIdx.x;
    int b = be / NE_;
    int p0 = mpos[be*M_+0]+1, p1 = mpos[be*M_+1]+1, p2 = mpos[be*M_+2]+1, p3 = mpos[be*M_+3]+1;
    const float* s = seq + (size_t)b * L_ * D_;
    for (int d = threadIdx.x; d < D_; d += blockDim.x) {
        float x0 = s[(size_t)p0*D_+d], x1 = s[(size_t)p1*D_+d];
        float x2 = s[(size_t)p2*D_+d], x3 = s[(size_t)p3*D_+d];
        float mx = fmaxf(fmaxf(x0,x1), fmaxf(x2,x3));
        float su = expf(x0-mx)+expf(x1-mx)+expf(x2-mx)+expf(x3-mx);
        g_ent_emb[(size_t)be*D_+d] = mx + logf(su);
    }
}

// ---------------- K2: entity attention = mean over 4 rows, stored [b,e,l,h] ----------------
__global__ void k_ent_att(const float* __restrict__ att, const int* __restrict__ mpos) {
    int idx = blockIdx.x;
    int be = idx / H_, h = idx % H_;
    int b = be / NE_;
    int p0 = mpos[be*M_+0]+1, p1 = mpos[be*M_+1]+1, p2 = mpos[be*M_+2]+1, p3 = mpos[be*M_+3]+1;
    const float* a = att + ((size_t)b*H_ + h) * L_ * L_;
    float* o = g_ent_att + (size_t)be * L_ * H_ + h;
    for (int l = threadIdx.x; l < L_; l += blockDim.x) {
        o[(size_t)l*H_] = 0.25f * (a[(size_t)p0*L_+l] + a[(size_t)p1*L_+l] +
                                   a[(size_t)p2*L_+l] + a[(size_t)p3*L_+l]);
    }
}

// ---------------- K3: normalized per-pair context attention ----------------
__global__ void k_pair_att(const int* __restrict__ hts) {
    int bp = blockIdx.x;
    int b = bp / P_;
    int hi = hts[bp*2+0], ti = hts[bp*2+1];
    const float* ei = g_ent_att + (size_t)(b*NE_ + hi) * L_ * H_;
    const float* ej = g_ent_att + (size_t)(b*NE_ + ti) * L_ * H_;
    float v[4];
    float loc = 0.0f;
    #pragma unroll
    for (int r = 0; r < 4; r++) {
        int l = threadIdx.x + r * 256;
        const float* pi = ei + (size_t)l * H_;
        const float* pj = ej + (size_t)l * H_;
        float acc = 0.0f;
        #pragma unroll
        for (int h = 0; h < H_; h++) acc += pi[h] * pj[h];
        acc *= (1.0f / (float)H_);
        v[r] = acc;
        loc += acc;
    }
    __shared__ float red[256];
    red[threadIdx.x] = loc;
    __syncthreads();
    for (int s = 128; s > 0; s >>= 1) {
        if (threadIdx.x < s) red[threadIdx.x] += red[threadIdx.x + s];
        __syncthreads();
    }
    float scale = 1.0f / (red[0] + 1e-5f);
    #pragma unroll
    for (int r = 0; r < 4; r++)
        g_pair_att[(size_t)bp*L_ + threadIdx.x + r*256] = v[r] * scale;
}

// ---------------- K4: rs = pair_att @ seq (per-batch), 128x128x16 fp32x2 GEMM ----------------
__global__ void k_rs(const float* __restrict__ seq) {
    __shared__ float As[16][128];
    __shared__ float Bs[16][128];
    int t = threadIdx.x;
    int m0 = blockIdx.y * 128, n0 = blockIdx.x * 128;
    int b = m0 / P_;
    const float* Bg = seq + (size_t)b * L_ * D_;
    const float* Ag = g_pair_att + (size_t)m0 * L_;
    int tm = t / 16, tn = t % 16;
    int arow = t >> 1, acol8 = (t & 1) * 8;
    int brow = t >> 4, bcol8 = (t & 15) * 8;
    u64 acc[8][4];
    #pragma unroll
    for (int i = 0; i < 8; i++)
        #pragma unroll
        for (int j = 0; j < 4; j++) acc[i][j] = 0ull;

    for (int k0 = 0; k0 < L_; k0 += 16) {
        float4 a0 = *(const float4*)(Ag + (size_t)arow*L_ + k0 + acol8);
        float4 a1 = *(const float4*)(Ag + (size_t)arow*L_ + k0 + acol8 + 4);
        float4 b0 = *(const float4*)(Bg + (size_t)(k0+brow)*D_ + n0 + bcol8);
        float4 b1 = *(const float4*)(Bg + (size_t)(k0+brow)*D_ + n0 + bcol8 + 4);
        __syncthreads();
        As[acol8+0][arow]=a0.x; As[acol8+1][arow]=a0.y; As[acol8+2][arow]=a0.z; As[acol8+3][arow]=a0.w;
        As[acol8+4][arow]=a1.x; As[acol8+5][arow]=a1.y; As[acol8+6][arow]=a1.z; As[acol8+7][arow]=a1.w;
        *(float4*)&Bs[brow][bcol8]   = b0;
        *(float4*)&Bs[brow][bcol8+4] = b1;
        __syncthreads();
        #pragma unroll
        for (int kk = 0; kk < 16; kk++) {
            float4 aA = *(const float4*)&As[kk][tm*8];
            float4 aB = *(const float4*)&As[kk][tm*8+4];
            ulonglong2 q0 = *(const ulonglong2*)&Bs[kk][tn*8];
            ulonglong2 q1 = *(const ulonglong2*)&Bs[kk][tn*8+4];
            u64 bv0=q0.x, bv1=q0.y, bv2=q1.x, bv3=q1.y;
            float am[8] = {aA.x,aA.y,aA.z,aA.w,aB.x,aB.y,aB.z,aB.w};
            #pragma unroll
            for (int i = 0; i < 8; i++) {
                u64 pa = pack2(am[i], am[i]);
                acc[i][0] = fma2(pa, bv0, acc[i][0]);
                acc[i][1] = fma2(pa, bv1, acc[i][1]);
                acc[i][2] = fma2(pa, bv2, acc[i][2]);
                acc[i][3] = fma2(pa, bv3, acc[i][3]);
            }
        }
    }
    #pragma unroll
    for (int i = 0; i < 8; i++) {
        float* out = g_rs + (size_t)(m0 + tm*8 + i) * D_ + n0 + tn*8;
        #pragma unroll
        for (int j = 0; j < 4; j++) {
            float2 v = unpack2(acc[i][j]);
            out[2*j] = v.x; out[2*j+1] = v.y;
        }
    }
}

// ---------------- K5: extractors zs/zo = tanh([ent|rs] @ W + b) ----------------
__global__ void k_ext(const int* __restrict__ hts,
                      const float* __restrict__ Wh, const float* __restrict__ bh,
                      const float* __restrict__ Wt, const float* __restrict__ bt) {
    __shared__ float As[16][128];
    __shared__ float Bs[16][128];
    int side = blockIdx.z;
    const float* W    = side ? Wt : Wh;
    const float* bias = side ? bt : bh;
    float* Cout       = side ? g_zo : g_zs;
    int t = threadIdx.x;
    int m0 = blockIdx.y * 128, n0 = blockIdx.x * 128;
    int tm = t / 16, tn = t % 16;
    int arow = t >> 1, acol8 = (t & 1) * 8;
    int brow = t >> 4, bcol8 = (t & 15) * 8;
    int np = m0 + arow;
    int b = np / P_;
    int eidx = hts[np*2 + side];
    const float* A0 = g_ent_emb + (size_t)(b*NE_ + eidx) * D_;
    const float* A1 = g_rs + (size_t)np * D_;
    u64 acc[8][4];
    #pragma unroll
    for (int i = 0; i < 8; i++)
        #pragma unroll
        for (int j = 0; j < 4; j++) acc[i][j] = 0ull;

    for (int k0 = 0; k0 < 2*D_; k0 += 16) {
        const float* Arow = (k0 < D_) ? (A0 + k0) : (A1 + (k0 - D_));
        float4 a0 = *(const float4*)(Arow + acol8);
        float4 a1 = *(const float4*)(Arow + acol8 + 4);
        float4 b0 = *(const float4*)(W + (size_t)(k0+brow)*D_ + n0 + bcol8);
        float4 b1 = *(const float4*)(W + (size_t)(k0+brow)*D_ + n0 + bcol8 + 4);
        __syncthreads();
        As[acol8+0][arow]=a0.x; As[acol8+1][arow]=a0.y; As[acol8+2][arow]=a0.z; As[acol8+3][arow]=a0.w;
        As[acol8+4][arow]=a1.x; As[acol8+5][arow]=a1.y; As[acol8+6][arow]=a1.z; As[acol8+7][arow]=a1.w;
        *(float4*)&Bs[brow][bcol8]   = b0;
        *(float4*)&Bs[brow][bcol8+4] = b1;
        __syncthreads();
        #pragma unroll
        for (int kk = 0; kk < 16; kk++) {
            float4 aA = *(const float4*)&As[kk][tm*8];
            float4 aB = *(const float4*)&As[kk][tm*8+4];
            ulonglong2 q0 = *(const ulonglong2*)&Bs[kk][tn*8];
            ulonglong2 q1 = *(const ulonglong2*)&Bs[kk][tn*8+4];
            u64 bv0=q0.x, bv1=q0.y, bv2=q1.x, bv3=q1.y;
            float am[8] = {aA.x,aA.y,aA.z,aA.w,aB.x,aB.y,aB.z,aB.w};
            #pragma unroll
            for (int i = 0; i < 8; i++) {
                u64 pa = pack2(am[i], am[i]);
                acc[i][0] = fma2(pa, bv0, acc[i][0]);
                acc[i][1] = fma2(pa, bv1, acc[i][1]);
                acc[i][2] = fma2(pa, bv2, acc[i][2]);
                acc[i][3] = fma2(pa, bv3, acc[i][3]);
            }
        }
    }
    #pragma unroll
    for (int i = 0; i < 8; i++) {
        float* out = Cout + (size_t)(m0 + tm*8 + i) * D_ + n0 + tn*8;
        #pragma unroll
        for (int j = 0; j < 4; j++) {
            float2 v = unpack2(acc[i][j]);
            int n = n0 + tn*8 + 2*j;
            out[2*j]   = tanhf(v.x + bias[n]);
            out[2*j+1] = tanhf(v.y + bias[n+1]);
        }
    }
}

// ---------------- K6 v2: bilinear partials ----------------
// Block: 128 pairs x 112 padded cols, half a 64-k-block (32 i values).
// 224 threads; thread tile = 8 pairs x 8 cols. W tiles streamed via cp.async
// double buffer. grid (16, 24): blockIdx.y = kk*2 + half.
#define ZPAD 132                 // row pad for Zs/Zo (16B-aligned, low conflict)
#define WSTILE (64*NLP_)         // floats per W buffer (7168)

__global__ void __launch_bounds__(224, 2) k_bil() {
    extern __shared__ float sm[];
    float* Ws = sm;                       // [2][64][112]
    float* Zs = sm + 2*WSTILE;            // [32][ZPAD]
    float* Zo = Zs + 32*ZPAD;             // [64][ZPAD]
    const int t = threadIdx.x;
    const int pb = blockIdx.x;
    const int ih = blockIdx.y;
    const int kk = ih >> 1, half = ih & 1;
    const int m0 = pb * 128;
    const int i0 = half * 32;

    // stage Zs: [i][m] = zs[m0+m][kk*64+i0+i], coalesced over i
    for (int idx = t; idx < 32*128; idx += 224) {
        int m = idx >> 5, i = idx & 31;
        Zs[i*ZPAD + m] = g_zs[(size_t)(m0+m)*D_ + kk*64 + i0 + i];
    }
    // stage Zo: [j][m] = zo[m0+m][kk*64+j], coalesced over j
    for (int idx = t; idx < 64*128; idx += 224) {
        int m = idx >> 6, j = idx & 63;
        Zo[j*ZPAD + m] = g_zo[(size_t)(m0+m)*D_ + kk*64 + j];
    }

    unsigned int ws_s = (unsigned int)__cvta_generic_to_shared(Ws);
    // prologue: async-load W tiles for i=0,1
    #pragma unroll
    for (int pre = 0; pre < 2; pre++) {
        const float4* src = (const float4*)(g_Wb + (size_t)(kk*64 + i0 + pre) * WSTILE);
        unsigned int dst = ws_s + (unsigned int)(pre * WSTILE * 4);
        #pragma unroll
        for (int q = 0; q < 8; q++)
            cpa16(dst + (unsigned int)((t + q*224) * 16), src + t + q*224);
        cpa_commit();
    }
    __syncthreads();   // Zs/Zo visible

    const int tm = t / 14, tn = t % 14;   // tm:16 (x8 pairs), tn:14 (x8 cols)
    u64 acc[8][4];
    #pragma unroll
    for (int p = 0; p < 8; p++)
        #pragma unroll
        for (int q = 0; q < 4; q++) acc[p][q] = 0ull;

    for (int i = 0; i < 32; i++) {
        cpa_wait<1>();
        __syncthreads();                  // W tile i ready for everyone
        const float* Wc = Ws + (i & 1) * WSTILE;

        float4 c0 = *(const float4*)&Zs[i*ZPAD + tm*8];
        float4 c1 = *(const float4*)&Zs[i*ZPAD + tm*8 + 4];
        float cm[8] = {c0.x,c0.y,c0.z,c0.w,c1.x,c1.y,c1.z,c1.w};

        #pragma unroll 4
        for (int j = 0; j < 64; j++) {
            const float* wr = Wc + j*NLP_ + tn*8;
            ulonglong2 qa = *(const ulonglong2*)wr;
            ulonglong2 qb = *(const ulonglong2*)(wr + 4);
            u64 w0 = qa.x, w1 = qa.y, w2 = qb.x, w3 = qb.y;
            float4 z0 = *(const float4*)&Zo[j*ZPAD + tm*8];
            float4 z1 = *(const float4*)&Zo[j*ZPAD + tm*8 + 4];
            float zm[8] = {z0.x,z0.y,z0.z,z0.w,z1.x,z1.y,z1.z,z1.w};
            #pragma unroll
            for (int p = 0; p < 8; p++) {
                float a = cm[p] * zm[p];
                u64 pa = pack2(a, a);
                acc[p][0] = fma2(pa, w0, acc[p][0]);
                acc[p][1] = fma2(pa, w1, acc[p][1]);
                acc[p][2] = fma2(pa, w2, acc[p][2]);
                acc[p][3] = fma2(pa, w3, acc[p][3]);
            }
        }
        __syncthreads();                  // done reading buffer (i&1)
        if (i + 2 < 32) {
            const float4* src = (const float4*)(g_Wb + (size_t)(kk*64 + i0 + i + 2) * WSTILE);
            unsigned int dst = ws_s + (unsigned int)((i & 1) * WSTILE * 4);
            #pragma unroll
            for (int q = 0; q < 8; q++)
                cpa16(dst + (unsigned int)((t + q*224) * 16), src + t + q*224);
        }
        cpa_commit();                     // keep group count in lockstep
    }

    #pragma unroll
    for (int p = 0; p < 8; p++) {
        float* out = g_part + ((size_t)ih * NPAIR_ + m0 + tm*8 + p) * NL_;
        #pragma unroll
        for (int q = 0; q < 4; q++) {
            float2 v = unpack2(acc[p][q]);
            int n = tn*8 + 2*q;
            if (n   < NL_) out[n]   = v.x;
            if (n+1 < NL_) out[n+1] = v.y;
        }
    }
}

// ---------------- K7: reduce K-splits + bias ----------------
__global__ void k_red(const float* __restrict__ bbi, float* __restrict__ out) {
    int i = blockIdx.x * blockDim.x + threadIdx.x;
    if (i < NPAIR_ * NL_) {
        int n = i % NL_;
        float s = bbi[n];
        #pragma unroll
        for (int k = 0; k < KS_; k++) s += g_part[(size_t)k * NPAIR_ * NL_ + i];
        out[i] = s;
    }
}

extern "C" void kernel_launch(void* const* d_in, const int* in_sizes, int n_in,
                              void* d_out, int out_size) {
    const float* seq  = (const float*)d_in[0];
    const float* att  = (const float*)d_in[1];
    const int*   mpos = (const int*)d_in[2];
    const int*   hts  = (const int*)d_in[3];
    const float* Wh   = (const float*)d_in[4];
    const float* bh   = (const float*)d_in[5];
    const float* Wt   = (const float*)d_in[6];
    const float* bt   = (const float*)d_in[7];
    const float* Wbi  = (const float*)d_in[8];
    const float* bbi  = (const float*)d_in[9];
    float* out = (float*)d_out;

    const int bil_smem = (2*WSTILE + 32*ZPAD + 64*ZPAD) * 4;   // 108032 B
    cudaFuncSetAttribute(k_bil, cudaFuncAttributeMaxDynamicSharedMemorySize, bil_smem);

    k_wpad<<<(KBI_*NLP_ + 255)/256, 256>>>(Wbi);
    k_ent_emb<<<B_*NE_, 256>>>(seq, mpos);
    k_ent_att<<<B_*NE_*H_, 256>>>(att, mpos);
    k_pair_att<<<NPAIR_, 256>>>(hts);
    k_rs<<<dim3(6, 16), 256>>>(seq);
    k_ext<<<dim3(6, 16, 2), 256>>>(hts, Wh, bh, Wt, bt);
    k_bil<<<dim3(16, 24), 224, bil_smem>>>();
    k_red<<<(NPAIR_*NL_ + 255)/256, 256>>>(bbi, out);
}